// round 1
// baseline (speedup 1.0000x reference)
#include <cuda_runtime.h>

#define D      256
#define TT     9
#define NTYPES 14
#define NSRC   5
#define PMAX   4
#define BM     128
#define BN     128
#define BK     16
#define E_MAX  131072

__constant__ int   c_base_map[NTYPES] = {0,0,0,1,1,1,2,2,3,4,5,6,7,8};
__constant__ int   c_pcount[TT]       = {2,2,1,1,1,1,3,2,4};
__constant__ float c_scales[TT][PMAX] = {
  {1.f,    1e-6f, 1.f,  1.f},   // nmos   m,w
  {1.f,    1e-6f, 1.f,  1.f},   // pmos   m,w
  {1.f,    1.f,   1.f,  1.f},   // balun  rout
  {1000.f, 1.f,   1.f,  1.f},   // resistor r
  {1e-12f, 1.f,   1.f,  1.f},   // capacitor c
  {1e-9f,  1.f,   1.f,  1.f},   // inductor l
  {1.f,    1.f,   1.f,  1.f},   // vsource dc,mag,phase
  {1e-3f,  1e-3f, 1.f,  1.f},   // isource dc,mag
  {1.f,    1.f,   1e9f, 1.f}    // port dbm,dc,freq,num
};

// ---- device scratch (no allocations allowed) ----
__device__ int   g_counts[TT];
__device__ int   g_offsets[TT+1];
__device__ int   g_cursor[TT];
__device__ int   g_tile_off[TT+1];
__device__ int   g_perm[E_MAX];
__device__ float g_W2f[TT][D][D];   // W2[t] @ Wf[512:768]
__device__ float g_b2f[TT][D];      // b2[t] @ Wf[512:768] + bf
__device__ float g_tc[NTYPES][D];   // type_embed @ Wf[0:256]
__device__ float g_sc[NSRC][D];     // source_embed @ Wf[256:512]

// ---- packed f32x2 helpers ----
__device__ __forceinline__ unsigned long long ffma2(unsigned long long a,
                                                    unsigned long long b,
                                                    unsigned long long c) {
  unsigned long long d;
  asm("fma.rn.f32x2 %0, %1, %2, %3;" : "=l"(d) : "l"(a), "l"(b), "l"(c));
  return d;
}
__device__ __forceinline__ unsigned long long dup2(float a) {
  unsigned long long v;
  asm("mov.b64 %0, {%1, %1};" : "=l"(v) : "f"(a));
  return v;
}
__device__ __forceinline__ float2 unpack2(unsigned long long v) {
  float2 r;
  asm("mov.b64 {%0, %1}, %2;" : "=f"(r.x), "=f"(r.y) : "l"(v));
  return r;
}

// ---------------- bucketing ----------------
__global__ void k_init() {
  int t = threadIdx.x;
  if (t < TT) g_counts[t] = 0;
}

__global__ void k_hist(const int* __restrict__ type_ids, int E) {
  __shared__ int lh[TT];
  int tid = threadIdx.x;
  if (tid < TT) lh[tid] = 0;
  __syncthreads();
  int e = blockIdx.x * blockDim.x + tid;
  if (e < E) atomicAdd(&lh[c_base_map[type_ids[e]]], 1);
  __syncthreads();
  if (tid < TT && lh[tid]) atomicAdd(&g_counts[tid], lh[tid]);
}

__global__ void k_scan() {
  int off = 0, toff = 0;
  for (int t = 0; t < TT; t++) {
    g_offsets[t]  = off;
    g_cursor[t]   = off;
    g_tile_off[t] = toff;
    off  += g_counts[t];
    toff += (g_counts[t] + BM - 1) / BM;
  }
  g_offsets[TT]  = off;
  g_tile_off[TT] = toff;
}

__global__ void k_scatter(const int* __restrict__ type_ids, int E) {
  __shared__ int lh[TT];
  __shared__ int lbase[TT];
  int tid = threadIdx.x;
  if (tid < TT) lh[tid] = 0;
  __syncthreads();
  int e = blockIdx.x * blockDim.x + tid;
  int b = 0, lpos = 0;
  if (e < E) {
    b = c_base_map[type_ids[e]];
    lpos = atomicAdd(&lh[b], 1);
  }
  __syncthreads();
  if (tid < TT) lbase[tid] = lh[tid] ? atomicAdd(&g_cursor[tid], lh[tid]) : 0;
  __syncthreads();
  if (e < E) g_perm[lbase[b] + lpos] = e;
}

// ---------------- table precompute ----------------
// 28 blocks: 14 type rows, 5 source rows, 9 b2f rows. One row of 256 per block.
__global__ void k_tables(const float* __restrict__ te, const float* __restrict__ se,
                         const float* __restrict__ b2, const float* __restrict__ Wf,
                         const float* __restrict__ bf) {
  __shared__ float row[D];
  int r = blockIdx.x, d = threadIdx.x;
  const float* src;
  const float* wbase;
  float* dst;
  float acc;
  if (r < NTYPES) {
    src = te + r * D;  wbase = Wf;            dst = &g_tc[r][0];          acc = 0.f;
  } else if (r < NTYPES + NSRC) {
    int s = r - NTYPES;
    src = se + s * D;  wbase = Wf + 256 * D;  dst = &g_sc[s][0];          acc = 0.f;
  } else {
    int t = r - NTYPES - NSRC;
    src = b2 + t * D;  wbase = Wf + 512 * D;  dst = &g_b2f[t][0];         acc = bf[d];
  }
  row[d] = src[d];
  __syncthreads();
  #pragma unroll 8
  for (int k = 0; k < D; k++) acc = fmaf(row[k], wbase[k * D + d], acc);
  dst[d] = acc;
}

// W2f[t][k][d] = sum_dp W2[t][k][dp] * Wf[512+dp][d]. 144 blocks, 16 k-rows each.
__global__ void k_w2f(const float* __restrict__ W2, const float* __restrict__ Wf) {
  __shared__ float sW2[16][D];
  int t  = blockIdx.x >> 4;
  int kg = blockIdx.x & 15;
  int d  = threadIdx.x;
  for (int kk = 0; kk < 16; kk++)
    sW2[kk][d] = W2[(t * D + kg * 16 + kk) * D + d];
  __syncthreads();
  float acc[16];
  #pragma unroll
  for (int kk = 0; kk < 16; kk++) acc[kk] = 0.f;
  const float* wb = Wf + 512 * D + d;
  for (int dp = 0; dp < D; dp++) {
    float wf = wb[dp * D];
    #pragma unroll
    for (int kk = 0; kk < 16; kk++) acc[kk] = fmaf(sW2[kk][dp], wf, acc[kk]);
  }
  #pragma unroll
  for (int kk = 0; kk < 16; kk++) g_W2f[t][kg * 16 + kk][d] = acc[kk];
}

// ---------------- main fused expert GEMM ----------------
__global__ __launch_bounds__(256) void k_main(
    const int* __restrict__ type_ids, const int* __restrict__ source_ids,
    const float* __restrict__ params, const float* __restrict__ W1,
    const float* __restrict__ b1, float* __restrict__ out) {
  __shared__ float sW1[PMAX][D];
  __shared__ float sb1[D];
  __shared__ float sxs[BM][PMAX];
  __shared__ int   s_pe[BM];
  __shared__ int   s_te[BM];
  __shared__ int   s_se[BM];
  __shared__ float sH[BK][BM];      // k-major h tile
  __shared__ float sB[BK][BN];      // W2f tile
  __shared__ float s_b2f[BN];

  int bx = blockIdx.x;
  if (bx >= g_tile_off[TT]) return;
  int t = 0;
  while (bx >= g_tile_off[t + 1]) t++;
  int lt   = bx - g_tile_off[t];
  int m0   = lt * BM;               // local row within this type's bucket
  int cnt  = g_counts[t];
  int base = g_offsets[t];
  int n0   = blockIdx.y * BN;
  int tid  = threadIdx.x;

  for (int i = tid; i < PMAX * D; i += 256) sW1[i >> 8][i & 255] = W1[t * PMAX * D + i];
  for (int i = tid; i < D; i += 256)        sb1[i] = b1[t * D + i];
  for (int i = tid; i < BN; i += 256)       s_b2f[i] = g_b2f[t][n0 + i];

  if (tid < BM) {
    int gm = m0 + tid;
    if (gm < cnt) {
      int e = g_perm[base + gm];
      s_pe[tid] = e;
      s_te[tid] = type_ids[e];
      s_se[tid] = source_ids[e];
      int pc = c_pcount[t];
      #pragma unroll
      for (int p = 0; p < PMAX; p++)
        sxs[tid][p] = (p < pc) ? params[e * PMAX + p] / c_scales[t][p] : 0.f;
    } else {
      s_pe[tid] = -1; s_te[tid] = 0; s_se[tid] = 0;
      #pragma unroll
      for (int p = 0; p < PMAX; p++) sxs[tid][p] = 0.f;
    }
  }
  __syncthreads();

  int ty = tid >> 4, tx = tid & 15;
  int mrow = ty * 8, ncol = tx * 8;

  unsigned long long acc[8][4];
  #pragma unroll
  for (int i = 0; i < 8; i++)
    #pragma unroll
    for (int j = 0; j < 4; j++) acc[i][j] = 0ull;

  const float* Bsrc = &g_W2f[t][0][n0];

  for (int k0 = 0; k0 < D; k0 += BK) {
    // compute h tile: h[m][k] = relu(b1[k] + sum_p x[m][p]*W1[p][k]), stored k-major
    #pragma unroll
    for (int it = 0; it < 8; it++) {
      int idx = tid + it * 256;
      int m  = idx & 127;
      int kk = idx >> 7;            // 0..15
      int k  = k0 + kk;
      float h = sb1[k];
      #pragma unroll
      for (int p = 0; p < PMAX; p++) h = fmaf(sxs[m][p], sW1[p][k], h);
      sH[kk][m] = fmaxf(h, 0.f);
    }
    // load W2f tile
    {
      int c = (tid & 31) << 2;
      int r = tid >> 5;
      #pragma unroll
      for (int rr = 0; rr < 2; rr++) {
        int kk = r + rr * 8;
        *(float4*)&sB[kk][c] = *(const float4*)&Bsrc[(k0 + kk) * D + c];
      }
    }
    __syncthreads();
    #pragma unroll
    for (int kk = 0; kk < BK; kk++) {
      unsigned long long bv[4];
      const unsigned long long* bp = (const unsigned long long*)&sB[kk][ncol];
      #pragma unroll
      for (int j = 0; j < 4; j++) bv[j] = bp[j];
      float4 alo = *(const float4*)&sH[kk][mrow];
      float4 ahi = *(const float4*)&sH[kk][mrow + 4];
      float av[8] = {alo.x, alo.y, alo.z, alo.w, ahi.x, ahi.y, ahi.z, ahi.w};
      #pragma unroll
      for (int i = 0; i < 8; i++) {
        unsigned long long ad = dup2(av[i]);
        #pragma unroll
        for (int j = 0; j < 4; j++) acc[i][j] = ffma2(ad, bv[j], acc[i][j]);
      }
    }
    __syncthreads();
  }

  // epilogue: add type/source/bias tables, relu, scatter rows back
  #pragma unroll
  for (int i = 0; i < 8; i++) {
    int m = mrow + i;
    if (m0 + m >= cnt) continue;
    int e = s_pe[m];
    const float* tcp = &g_tc[s_te[m]][n0 + ncol];
    const float* scp = &g_sc[s_se[m]][n0 + ncol];
    float4 t0 = *(const float4*)&tcp[0];
    float4 t1 = *(const float4*)&tcp[4];
    float4 c0 = *(const float4*)&scp[0];
    float4 c1 = *(const float4*)&scp[4];
    float2 p0 = unpack2(acc[i][0]);
    float2 p1 = unpack2(acc[i][1]);
    float2 p2 = unpack2(acc[i][2]);
    float2 p3 = unpack2(acc[i][3]);
    float4 o0, o1;
    o0.x = fmaxf(p0.x + t0.x + c0.x + s_b2f[ncol + 0], 0.f);
    o0.y = fmaxf(p0.y + t0.y + c0.y + s_b2f[ncol + 1], 0.f);
    o0.z = fmaxf(p1.x + t0.z + c0.z + s_b2f[ncol + 2], 0.f);
    o0.w = fmaxf(p1.y + t0.w + c0.w + s_b2f[ncol + 3], 0.f);
    o1.x = fmaxf(p2.x + t1.x + c1.x + s_b2f[ncol + 4], 0.f);
    o1.y = fmaxf(p2.y + t1.y + c1.y + s_b2f[ncol + 5], 0.f);
    o1.z = fmaxf(p3.x + t1.z + c1.z + s_b2f[ncol + 6], 0.f);
    o1.w = fmaxf(p3.y + t1.w + c1.w + s_b2f[ncol + 7], 0.f);
    float* op = out + (size_t)e * D + n0 + ncol;
    *(float4*)&op[0] = o0;
    *(float4*)&op[4] = o1;
  }
}

extern "C" void kernel_launch(void* const* d_in, const int* in_sizes, int n_in,
                              void* d_out, int out_size) {
  const int*   type_ids     = (const int*)d_in[0];
  const int*   source_ids   = (const int*)d_in[1];
  const float* params       = (const float*)d_in[2];
  const float* type_embed   = (const float*)d_in[3];
  const float* source_embed = (const float*)d_in[4];
  const float* W1           = (const float*)d_in[5];
  const float* b1           = (const float*)d_in[6];
  const float* W2           = (const float*)d_in[7];
  const float* b2           = (const float*)d_in[8];
  const float* Wf           = (const float*)d_in[9];
  const float* bf           = (const float*)d_in[10];
  float* out = (float*)d_out;
  int E = in_sizes[0];
  if (E > E_MAX) E = E_MAX;

  k_init<<<1, 32>>>();
  int nb = (E + 255) / 256;
  k_hist<<<nb, 256>>>(type_ids, E);
  k_scan<<<1, 1>>>();
  k_scatter<<<nb, 256>>>(type_ids, E);
  k_tables<<<NTYPES + NSRC + TT, 256>>>(type_embed, source_embed, b2, Wf, bf);
  k_w2f<<<TT * 16, 256>>>(W2, Wf);

  int tiles = (E + BM - 1) / BM + TT;   // upper bound on sum of per-type tiles
  dim3 g(tiles, D / BN);
  k_main<<<g, 256>>>(type_ids, source_ids, params, W1, b1, out);
}

// round 3
// speedup vs baseline: 1.6688x; 1.6688x over previous
#include <cuda_runtime.h>
#include <cuda_bf16.h>
#include <cstdint>

#define D      256
#define TT     9
#define NTYPES 14
#define NSRC   5
#define PMAX   4
#define BM     128
#define E_MAX  131072

// ---- dynamic SMEM layout (bytes) ----
#define SM_XS   0                    // 128 x float4        2048
#define SM_E    2048                 // 128 x int            512
#define SM_TE   2560
#define SM_SE   3072
#define SM_B2F  3584                 // 256 x float         1024
#define SM_W1T  4608                 // 256 x float4        4096
#define SM_B1   8704                 // 256 x float         1024
#define SM_A    10240                // 2 x 128 x 528B   135168  (hi, lo)
#define SM_ALO  (SM_A + 67584)
#define SM_SB   145408               // 2 x 16 x 528B     16896
#define SM_TOTAL 162304
#define LDAB    528                  // row pitch bytes (264 bf16)

__constant__ int   c_base_map[NTYPES] = {0,0,0,1,1,1,2,2,3,4,5,6,7,8};
__constant__ int   c_pcount[TT]       = {2,2,1,1,1,1,3,2,4};
__constant__ float c_scales[TT][PMAX] = {
  {1.f,1e-6f,1.f,1.f},{1.f,1e-6f,1.f,1.f},{1.f,1.f,1.f,1.f},
  {1000.f,1.f,1.f,1.f},{1e-12f,1.f,1.f,1.f},{1e-9f,1.f,1.f,1.f},
  {1.f,1.f,1.f,1.f},{1e-3f,1e-3f,1.f,1.f},{1.f,1.f,1e9f,1.f}
};

// ---- device scratch ----
__device__ int   g_counts[TT];
__device__ int   g_offsets[TT+1];
__device__ int   g_cursor[TT];
__device__ int   g_tile_off[TT+1];
__device__ int   g_perm[E_MAX];
__device__ __align__(16) __nv_bfloat16 g_B[TT][2][256][256];  // [t][hi/lo][k][n]
__device__ float g_b2f[TT][D];
__device__ float g_tc[NTYPES][D];
__device__ float g_sc[NSRC][D];

// ================= PTX helpers (sm_80-compatible only) =================
__device__ __forceinline__ uint32_t smem_u32(const void* p) {
  uint32_t a;
  asm("{ .reg .u64 t; cvta.to.shared.u64 t, %1; cvt.u32.u64 %0, t; }" : "=r"(a) : "l"(p));
  return a;
}
__device__ __forceinline__ void cp16(uint32_t dst, const void* src) {
  asm volatile("cp.async.cg.shared.global [%0], [%1], 16;" :: "r"(dst), "l"(src) : "memory");
}
__device__ __forceinline__ void ldm_x4(uint32_t* r, uint32_t a) {
  asm volatile("ldmatrix.sync.aligned.m8n8.x4.shared.b16 {%0,%1,%2,%3}, [%4];"
    : "=r"(r[0]),"=r"(r[1]),"=r"(r[2]),"=r"(r[3]) : "r"(a));
}
__device__ __forceinline__ void ldm_x4t(uint32_t* r, uint32_t a) {
  asm volatile("ldmatrix.sync.aligned.m8n8.x4.trans.shared.b16 {%0,%1,%2,%3}, [%4];"
    : "=r"(r[0]),"=r"(r[1]),"=r"(r[2]),"=r"(r[3]) : "r"(a));
}
__device__ __forceinline__ void mma16816(float* c, const uint32_t* a, uint32_t b0, uint32_t b1) {
  asm("mma.sync.aligned.m16n8k16.row.col.f32.bf16.bf16.f32 "
      "{%0,%1,%2,%3}, {%4,%5,%6,%7}, {%8,%9}, {%0,%1,%2,%3};"
      : "+f"(c[0]),"+f"(c[1]),"+f"(c[2]),"+f"(c[3])
      : "r"(a[0]),"r"(a[1]),"r"(a[2]),"r"(a[3]), "r"(b0),"r"(b1));
}

// ================= bucketing =================
__global__ void k_init() { if (threadIdx.x < TT) g_counts[threadIdx.x] = 0; }

__global__ void k_hist(const int* __restrict__ type_ids, int E) {
  __shared__ int lh[TT];
  int tid = threadIdx.x;
  if (tid < TT) lh[tid] = 0;
  __syncthreads();
  int e = blockIdx.x * blockDim.x + tid;
  if (e < E) atomicAdd(&lh[c_base_map[type_ids[e]]], 1);
  __syncthreads();
  if (tid < TT && lh[tid]) atomicAdd(&g_counts[tid], lh[tid]);
}

__global__ void k_scan() {
  int off = 0, toff = 0;
  for (int t = 0; t < TT; t++) {
    g_offsets[t] = off; g_cursor[t] = off; g_tile_off[t] = toff;
    off += g_counts[t];
    toff += (g_counts[t] + BM - 1) / BM;
  }
  g_offsets[TT] = off; g_tile_off[TT] = toff;
}

__global__ void k_scatter(const int* __restrict__ type_ids, int E) {
  __shared__ int lh[TT];
  __shared__ int lbase[TT];
  int tid = threadIdx.x;
  if (tid < TT) lh[tid] = 0;
  __syncthreads();
  int e = blockIdx.x * blockDim.x + tid;
  int b = 0, lpos = 0;
  if (e < E) { b = c_base_map[type_ids[e]]; lpos = atomicAdd(&lh[b], 1); }
  __syncthreads();
  if (tid < TT) lbase[tid] = lh[tid] ? atomicAdd(&g_cursor[tid], lh[tid]) : 0;
  __syncthreads();
  if (e < E) g_perm[lbase[b] + lpos] = e;
}

// ================= prologue tables =================
__global__ void k_tables(const float* __restrict__ te, const float* __restrict__ se,
                         const float* __restrict__ b2, const float* __restrict__ Wf,
                         const float* __restrict__ bf) {
  __shared__ float row[D];
  int r = blockIdx.x, d = threadIdx.x;
  const float* src; const float* wbase; float* dst; float acc;
  if (r < NTYPES)             { src = te + r * D;            wbase = Wf;           dst = &g_tc[r][0]; acc = 0.f; }
  else if (r < NTYPES + NSRC) { int s = r - NTYPES; src = se + s * D; wbase = Wf + 256 * D; dst = &g_sc[s][0]; acc = 0.f; }
  else                        { int t = r - NTYPES - NSRC; src = b2 + t * D; wbase = Wf + 512 * D; dst = &g_b2f[t][0]; acc = bf[d]; }
  row[d] = src[d];
  __syncthreads();
  #pragma unroll 8
  for (int k = 0; k < D; k++) acc = fmaf(row[k], wbase[k * D + d], acc);
  dst[d] = acc;
}

// W2f[k][d] = sum_dp W2[t][k][dp]*Wf[512+dp][d]; store bf16 hi + lo residual.
__global__ void k_w2f(const float* __restrict__ W2, const float* __restrict__ Wf) {
  __shared__ float sW2[16][D];
  int t  = blockIdx.x >> 4;
  int kg = blockIdx.x & 15;
  int d  = threadIdx.x;
  for (int kk = 0; kk < 16; kk++)
    sW2[kk][d] = W2[(t * D + kg * 16 + kk) * D + d];
  __syncthreads();
  float acc[16];
  #pragma unroll
  for (int kk = 0; kk < 16; kk++) acc[kk] = 0.f;
  const float* wb = Wf + 512 * D + d;
  for (int dp = 0; dp < D; dp++) {
    float wf = wb[dp * D];
    #pragma unroll
    for (int kk = 0; kk < 16; kk++) acc[kk] = fmaf(sW2[kk][dp], wf, acc[kk]);
  }
  #pragma unroll
  for (int kk = 0; kk < 16; kk++) {
    int k = kg * 16 + kk;
    float v = acc[kk];
    __nv_bfloat16 hi = __float2bfloat16(v);
    __nv_bfloat16 lo = __float2bfloat16(v - __bfloat162float(hi));
    g_B[t][0][k][d] = hi;
    g_B[t][1][k][d] = lo;
  }
}

// ================= main HMMA kernel =================
// 512 threads = 16 warps, warp grid 4(M) x 4(N); warp tile 32x64.
// A_cat = [h_hi | h_hi | h_lo] (K=768), B rows = [hi | lo | hi].
__global__ __launch_bounds__(512, 1) void k_main(
    const int* __restrict__ type_ids, const int* __restrict__ source_ids,
    const float* __restrict__ params, const float* __restrict__ W1,
    const float* __restrict__ b1, float* __restrict__ out) {
  extern __shared__ char smem[];
  int bx = blockIdx.x;
  if (bx >= g_tile_off[TT]) return;
  int t = 0;
  while (bx >= g_tile_off[t + 1]) t++;
  int lt = bx - g_tile_off[t], m0 = lt * BM, cnt = g_counts[t], base = g_offsets[t];
  int tid = threadIdx.x;
  uint32_t sb = smem_u32(smem);

  // issue cp.async for k-step 0 (pass 0 -> B hi, k0=0), overlap with setup
  {
    int row = tid >> 5, c8 = (tid & 31) * 8;
    cp16(sb + SM_SB + row * LDAB + c8 * 2, &g_B[t][0][row][c8]);
    asm volatile("cp.async.commit_group;" ::: "memory");
  }

  // metadata + weights
  if (tid < 128) {
    int gm = m0 + tid; int e = -1, tev = 0, sev = 0;
    float4 xv = {0.f, 0.f, 0.f, 0.f};
    if (gm < cnt) {
      e = g_perm[base + gm]; tev = type_ids[e]; sev = source_ids[e];
      int pc = c_pcount[t];
      float4 p4 = *(const float4*)&params[e * PMAX];
      xv.x = p4.x / c_scales[t][0];
      xv.y = pc > 1 ? p4.y / c_scales[t][1] : 0.f;
      xv.z = pc > 2 ? p4.z / c_scales[t][2] : 0.f;
      xv.w = pc > 3 ? p4.w / c_scales[t][3] : 0.f;
    }
    ((float4*)(smem + SM_XS))[tid] = xv;
    ((int*)(smem + SM_E))[tid]  = e;
    ((int*)(smem + SM_TE))[tid] = tev;
    ((int*)(smem + SM_SE))[tid] = sev;
  } else if (tid < 384) {
    int k = tid - 128;
    float4 w;
    w.x = W1[(t * PMAX + 0) * D + k];
    w.y = W1[(t * PMAX + 1) * D + k];
    w.z = W1[(t * PMAX + 2) * D + k];
    w.w = W1[(t * PMAX + 3) * D + k];
    ((float4*)(smem + SM_W1T))[k] = w;
    ((float*)(smem + SM_B1))[k] = b1[t * D + k];
  } else {
    int k = tid - 384;
    ((float*)(smem + SM_B2F))[k]       = g_b2f[t][k];
    ((float*)(smem + SM_B2F))[k + 128] = g_b2f[t][k + 128];
  }
  __syncthreads();

  // ---- A-phase: h = relu(x@W1+b1) -> bf16 hi/lo in SMEM ----
  {
    const float4* w1t = (const float4*)(smem + SM_W1T);
    const float*  sb1 = (const float*)(smem + SM_B1);
    const float4* xs  = (const float4*)(smem + SM_XS);
    #pragma unroll
    for (int it = 0; it < 16; it++) {
      int idx = tid + it * 512;
      int m = idx >> 6, kq = idx & 63;
      int k = kq * 4;
      float4 x = xs[m];
      uint32_t hw[2], lw[2];
      #pragma unroll
      for (int u = 0; u < 2; u++) {
        float h[2], r[2];
        #pragma unroll
        for (int v = 0; v < 2; v++) {
          float4 w = w1t[k + u * 2 + v];
          float hh = fmaf(x.x, w.x, fmaf(x.y, w.y, fmaf(x.z, w.z, fmaf(x.w, w.w, sb1[k + u * 2 + v]))));
          h[v] = fmaxf(hh, 0.f);
        }
        asm("cvt.rn.bf16x2.f32 %0, %1, %2;" : "=r"(hw[u]) : "f"(h[1]), "f"(h[0]));
        __nv_bfloat162 hb = *reinterpret_cast<__nv_bfloat162*>(&hw[u]);
        r[0] = h[0] - __bfloat162float(hb.x);
        r[1] = h[1] - __bfloat162float(hb.y);
        asm("cvt.rn.bf16x2.f32 %0, %1, %2;" : "=r"(lw[u]) : "f"(r[1]), "f"(r[0]));
      }
      uint32_t off = (uint32_t)m * LDAB + (uint32_t)k * 2;
      *(uint2*)(smem + SM_A   + off) = make_uint2(hw[0], hw[1]);
      *(uint2*)(smem + SM_ALO + off) = make_uint2(lw[0], lw[1]);
    }
  }
  __syncthreads();

  // ---- main loop: 48 k16-steps (3 passes x 16), 2-stage cp.async on B ----
  int w = tid >> 5, lane = tid & 31;
  int wm = w >> 2, wn = w & 3;
  float acc[2][8][4];
  #pragma unroll
  for (int i = 0; i < 2; i++)
    #pragma unroll
    for (int j = 0; j < 8; j++)
      #pragma unroll
      for (int q = 0; q < 4; q++) acc[i][j][q] = 0.f;

  uint32_t a_lrow = (uint32_t)(lane & 15);
  uint32_t a_koff = (lane & 16) ? 16u : 0u;             // bytes
  uint32_t b_noff = (uint32_t)(wn * 64 + ((lane & 16) ? 8 : 0)) * 2;
  int cp_row = tid >> 5, cp_c8 = (tid & 31) * 8;

  for (int s = 0; s < 48; s++) {
    int buf = s & 1;
    asm volatile("cp.async.wait_group 0;" ::: "memory");
    __syncthreads();
    if (s + 1 < 48) {
      int s1 = s + 1;
      int bsel = ((s1 >> 4) == 1) ? 1 : 0;
      int k1 = (s1 & 15) * 16;
      cp16(sb + SM_SB + (uint32_t)(1 - buf) * 8448 + cp_row * LDAB + cp_c8 * 2,
           &g_B[t][bsel][k1 + cp_row][cp_c8]);
    }
    asm volatile("cp.async.commit_group;" ::: "memory");

    int p = s >> 4, kk = s & 15;
    uint32_t abase = sb + (uint32_t)((p == 2) ? SM_ALO : SM_A) + (uint32_t)kk * 32 + a_koff;
    uint32_t ar[2][4];
    #pragma unroll
    for (int i = 0; i < 2; i++)
      ldm_x4(ar[i], abase + (uint32_t)(wm * 32 + i * 16 + a_lrow) * LDAB);

    uint32_t bbase = sb + SM_SB + (uint32_t)buf * 8448 + (uint32_t)(lane & 15) * LDAB + b_noff;
    uint32_t br[4][4];
    #pragma unroll
    for (int j = 0; j < 4; j++) ldm_x4t(br[j], bbase + (uint32_t)j * 32);

    #pragma unroll
    for (int i = 0; i < 2; i++)
      #pragma unroll
      for (int j = 0; j < 4; j++) {
        mma16816(acc[i][2 * j + 0], ar[i], br[j][0], br[j][1]);
        mma16816(acc[i][2 * j + 1], ar[i], br[j][2], br[j][3]);
      }
  }

  // ---- epilogue: tables + relu + scatter ----
  const float* sB2F = (const float*)(smem + SM_B2F);
  const int* sE  = (const int*)(smem + SM_E);
  const int* sTE = (const int*)(smem + SM_TE);
  const int* sSE = (const int*)(smem + SM_SE);
  #pragma unroll
  for (int i = 0; i < 2; i++) {
    #pragma unroll
    for (int rr = 0; rr < 2; rr++) {
      int ml = wm * 32 + i * 16 + (lane >> 2) + rr * 8;
      int e = sE[ml];
      if (e < 0) continue;
      const float* tcp = &g_tc[sTE[ml]][0];
      const float* scp = &g_sc[sSE[ml]][0];
      float* op = out + (size_t)e * D;
      #pragma unroll
      for (int jn = 0; jn < 8; jn++) {
        int col = wn * 64 + jn * 8 + (lane & 3) * 2;
        float2 tv = *(const float2*)&tcp[col];
        float2 sv = *(const float2*)&scp[col];
        float v0 = acc[i][jn][rr * 2 + 0] + tv.x + sv.x + sB2F[col];
        float v1 = acc[i][jn][rr * 2 + 1] + tv.y + sv.y + sB2F[col + 1];
        float2 o;
        o.x = fmaxf(v0, 0.f);
        o.y = fmaxf(v1, 0.f);
        *(float2*)&op[col] = o;
      }
    }
  }
}

// ================= launch =================
extern "C" void kernel_launch(void* const* d_in, const int* in_sizes, int n_in,
                              void* d_out, int out_size) {
  const int*   type_ids     = (const int*)d_in[0];
  const int*   source_ids   = (const int*)d_in[1];
  const float* params       = (const float*)d_in[2];
  const float* type_embed   = (const float*)d_in[3];
  const float* source_embed = (const float*)d_in[4];
  const float* W1           = (const float*)d_in[5];
  const float* b1           = (const float*)d_in[6];
  const float* W2           = (const float*)d_in[7];
  const float* b2           = (const float*)d_in[8];
  const float* Wf           = (const float*)d_in[9];
  const float* bf           = (const float*)d_in[10];
  float* out = (float*)d_out;
  int E = in_sizes[0];
  if (E > E_MAX) E = E_MAX;

  cudaFuncSetAttribute(k_main, cudaFuncAttributeMaxDynamicSharedMemorySize, SM_TOTAL);

  k_init<<<1, 32>>>();
  int nb = (E + 255) / 256;
  k_hist<<<nb, 256>>>(type_ids, E);
  k_scan<<<1, 1>>>();
  k_scatter<<<nb, 256>>>(type_ids, E);
  k_tables<<<NTYPES + NSRC + TT, 256>>>(type_embed, source_embed, b2, Wf, bf);
  k_w2f<<<TT * 16, 256>>>(W2, Wf);

  int tiles = (E + BM - 1) / BM + TT;
  k_main<<<tiles, 512, SM_TOTAL>>>(type_ids, source_ids, params, W1, b1, out);
}

// round 4
// speedup vs baseline: 1.7766x; 1.0646x over previous
#include <cuda_runtime.h>
#include <cuda_fp16.h>
#include <cstdint>

#define D      256
#define TT     9
#define NTYPES 14
#define NSRC   5
#define PMAX   4
#define BM     128
#define E_MAX  131072
#define NBMAX  512

// ---- dynamic SMEM layout (bytes) ----
#define SM_XS   0                    // 128 x float4        2048
#define SM_E    2048
#define SM_TE   2560
#define SM_SE   3072
#define SM_B2F  3584                 // 256 x float         1024
#define SM_W1T  4608                 // 256 x float4        4096
#define SM_B1   8704                 // 256 x float         1024
#define SM_A    9728                 // 128 x 528B        67584
#define SM_SB   77312                // 2 stages x 32 x 528B = 33792
#define SM_TOTAL 111104
#define LDAB    528                  // row pitch bytes
#define STAGE   16896                // 32 rows x 528

__constant__ int   c_base_map[NTYPES] = {0,0,0,1,1,1,2,2,3,4,5,6,7,8};
__constant__ int   c_pcount[TT]       = {2,2,1,1,1,1,3,2,4};
__constant__ float c_scales[TT][PMAX] = {
  {1.f,1e-6f,1.f,1.f},{1.f,1e-6f,1.f,1.f},{1.f,1.f,1.f,1.f},
  {1000.f,1.f,1.f,1.f},{1e-12f,1.f,1.f,1.f},{1e-9f,1.f,1.f,1.f},
  {1.f,1.f,1.f,1.f},{1e-3f,1e-3f,1.f,1.f},{1.f,1.f,1e9f,1.f}
};

// ---- device scratch ----
__device__ int   g_part[NBMAX][TT];
__device__ int   g_bbase[NBMAX][TT];
__device__ int   g_counts[TT];
__device__ int   g_offsets[TT+1];
__device__ int   g_tile_off[TT+1];
__device__ int   g_perm[E_MAX];
__device__ __align__(16) __half g_B[TT][2][256][256];  // [t][hi/lo][k][n]
__device__ float g_b2f[TT][D];
__device__ float g_tc[NTYPES][D];
__device__ float g_sc[NSRC][D];

// ================= PTX helpers =================
__device__ __forceinline__ uint32_t smem_u32(const void* p) {
  uint32_t a;
  asm("{ .reg .u64 t; cvta.to.shared.u64 t, %1; cvt.u32.u64 %0, t; }" : "=r"(a) : "l"(p));
  return a;
}
__device__ __forceinline__ void cp16(uint32_t dst, const void* src) {
  asm volatile("cp.async.cg.shared.global [%0], [%1], 16;" :: "r"(dst), "l"(src) : "memory");
}
__device__ __forceinline__ void ldm_x4(uint32_t* r, uint32_t a) {
  asm volatile("ldmatrix.sync.aligned.m8n8.x4.shared.b16 {%0,%1,%2,%3}, [%4];"
    : "=r"(r[0]),"=r"(r[1]),"=r"(r[2]),"=r"(r[3]) : "r"(a));
}
__device__ __forceinline__ void ldm_x4t(uint32_t* r, uint32_t a) {
  asm volatile("ldmatrix.sync.aligned.m8n8.x4.trans.shared.b16 {%0,%1,%2,%3}, [%4];"
    : "=r"(r[0]),"=r"(r[1]),"=r"(r[2]),"=r"(r[3]) : "r"(a));
}
__device__ __forceinline__ void mma16816(float* c, const uint32_t* a, uint32_t b0, uint32_t b1) {
  asm("mma.sync.aligned.m16n8k16.row.col.f32.f16.f16.f32 "
      "{%0,%1,%2,%3}, {%4,%5,%6,%7}, {%8,%9}, {%0,%1,%2,%3};"
      : "+f"(c[0]),"+f"(c[1]),"+f"(c[2]),"+f"(c[3])
      : "r"(a[0]),"r"(a[1]),"r"(a[2]),"r"(a[3]), "r"(b0),"r"(b1));
}

// ================= launch 0: per-block histogram =================
__global__ void k_hist(const int* __restrict__ type_ids, int E) {
  __shared__ int lh[TT];
  int tid = threadIdx.x, b = blockIdx.x;
  if (tid < TT) lh[tid] = 0;
  __syncthreads();
  int e = b * blockDim.x + tid;
  if (e < E) atomicAdd(&lh[c_base_map[type_ids[e]]], 1);
  __syncthreads();
  if (tid < TT) g_part[b][tid] = lh[tid];
}

// ================= launch 1: fused w2f + tables + scan =================
__global__ void k_fused(const float* __restrict__ te, const float* __restrict__ se,
                        const float* __restrict__ b2, const float* __restrict__ Wf,
                        const float* __restrict__ bf, const float* __restrict__ W2,
                        int nb) {
  int bx = blockIdx.x, d = threadIdx.x;
  if (bx < 144) {
    // ---- W2f = W2[t] @ Wf[512:768], fp16 hi + fp16 lo ----
    __shared__ float sW2[16][D];
    int t = bx >> 4, kg = bx & 15;
    for (int kk = 0; kk < 16; kk++)
      sW2[kk][d] = W2[(t * D + kg * 16 + kk) * D + d];
    __syncthreads();
    float acc[16];
    #pragma unroll
    for (int kk = 0; kk < 16; kk++) acc[kk] = 0.f;
    const float* wb = Wf + 512 * D + d;
    for (int dp = 0; dp < D; dp++) {
      float wf = wb[dp * D];
      #pragma unroll
      for (int kk = 0; kk < 16; kk++) acc[kk] = fmaf(sW2[kk][dp], wf, acc[kk]);
    }
    #pragma unroll
    for (int kk = 0; kk < 16; kk++) {
      int k = kg * 16 + kk;
      float v = acc[kk];
      __half hi = __float2half(v);
      __half lo = __float2half(v - __half2float(hi));
      g_B[t][0][k][d] = hi;
      g_B[t][1][k][d] = lo;
    }
  } else if (bx < 172) {
    // ---- embedding / bias tables ----
    __shared__ float row[D];
    int r = bx - 144;
    const float* src; const float* wbase; float* dst; float acc;
    if (r < NTYPES)             { src = te + r * D;            wbase = Wf;           dst = &g_tc[r][0]; acc = 0.f; }
    else if (r < NTYPES + NSRC) { int s = r - NTYPES; src = se + s * D; wbase = Wf + 256 * D; dst = &g_sc[s][0]; acc = 0.f; }
    else                        { int t = r - NTYPES - NSRC; src = b2 + t * D; wbase = Wf + 512 * D; dst = &g_b2f[t][0]; acc = bf[d]; }
    row[d] = src[d];
    __syncthreads();
    #pragma unroll 8
    for (int k = 0; k < D; k++) acc = fmaf(row[k], wbase[k * D + d], acc);
    dst[d] = acc;
  } else {
    // ---- scan: per-block bases + type offsets ----
    if (d < TT) {
      int run = 0;
      for (int b = 0; b < nb; b++) { g_bbase[b][d] = run; run += g_part[b][d]; }
      g_counts[d] = run;
    }
    __syncthreads();
    if (d == 0) {
      int off = 0, toff = 0;
      for (int t = 0; t < TT; t++) {
        g_offsets[t] = off; g_tile_off[t] = toff;
        off += g_counts[t];
        toff += (g_counts[t] + BM - 1) / BM;
      }
      g_offsets[TT] = off; g_tile_off[TT] = toff;
    }
  }
}

// ================= launch 2: scatter =================
__global__ void k_scatter(const int* __restrict__ type_ids, int E) {
  __shared__ int lh[TT];
  int tid = threadIdx.x, b = blockIdx.x;
  if (tid < TT) lh[tid] = 0;
  __syncthreads();
  int e = b * blockDim.x + tid;
  if (e < E) {
    int t = c_base_map[type_ids[e]];
    int lpos = atomicAdd(&lh[t], 1);
    g_perm[g_offsets[t] + g_bbase[b][t] + lpos] = e;
  }
}

// ================= launch 3: main HMMA kernel =================
// 512 threads = 16 warps, warp grid 4(M) x 4(N); warp tile 32x64.
// 2 passes folded per k-iter: acc += A_f16 x (B_hi + B_lo), K=256 per pass.
__global__ __launch_bounds__(512, 1) void k_main(
    const int* __restrict__ type_ids, const int* __restrict__ source_ids,
    const float* __restrict__ params, const float* __restrict__ W1,
    const float* __restrict__ b1, float* __restrict__ out) {
  extern __shared__ char smem[];
  int bx = blockIdx.x;
  if (bx >= g_tile_off[TT]) return;
  int t = 0;
  while (bx >= g_tile_off[t + 1]) t++;
  int lt = bx - g_tile_off[t], m0 = lt * BM, cnt = g_counts[t], base = g_offsets[t];
  int tid = threadIdx.x;
  uint32_t sb = smem_u32(smem);

  // prefetch k-iter 0 (B hi rows 0-15, lo rows 16-31) into stage 0
  int cp_row = tid >> 4, cp_c = (tid & 15) * 16;   // 16 halves = 32B per thread
  {
    const __half* src = (cp_row < 16) ? &g_B[t][0][cp_row][cp_c]
                                      : &g_B[t][1][cp_row - 16][cp_c];
    uint32_t dst = sb + SM_SB + (uint32_t)cp_row * LDAB + (uint32_t)cp_c * 2;
    cp16(dst, src);
    cp16(dst + 16, src + 8);
    asm volatile("cp.async.commit_group;" ::: "memory");
  }

  // metadata + weights
  if (tid < 128) {
    int gm = m0 + tid; int e = -1, tev = 0, sev = 0;
    float4 xv = {0.f, 0.f, 0.f, 0.f};
    if (gm < cnt) {
      e = g_perm[base + gm]; tev = type_ids[e]; sev = source_ids[e];
      int pc = c_pcount[t];
      float4 p4 = *(const float4*)&params[e * PMAX];
      xv.x = p4.x / c_scales[t][0];
      xv.y = pc > 1 ? p4.y / c_scales[t][1] : 0.f;
      xv.z = pc > 2 ? p4.z / c_scales[t][2] : 0.f;
      xv.w = pc > 3 ? p4.w / c_scales[t][3] : 0.f;
    }
    ((float4*)(smem + SM_XS))[tid] = xv;
    ((int*)(smem + SM_E))[tid]  = e;
    ((int*)(smem + SM_TE))[tid] = tev;
    ((int*)(smem + SM_SE))[tid] = sev;
  } else if (tid < 384) {
    int k = tid - 128;
    float4 w;
    w.x = W1[(t * PMAX + 0) * D + k];
    w.y = W1[(t * PMAX + 1) * D + k];
    w.z = W1[(t * PMAX + 2) * D + k];
    w.w = W1[(t * PMAX + 3) * D + k];
    ((float4*)(smem + SM_W1T))[k] = w;
    ((float*)(smem + SM_B1))[k] = b1[t * D + k];
  } else {
    int k = tid - 384;
    ((float*)(smem + SM_B2F))[k]       = g_b2f[t][k];
    ((float*)(smem + SM_B2F))[k + 128] = g_b2f[t][k + 128];
  }
  __syncthreads();

  // ---- A-phase: h = relu(x@W1+b1) -> fp16 in SMEM ----
  {
    const float4* w1t = (const float4*)(smem + SM_W1T);
    const float*  sb1 = (const float*)(smem + SM_B1);
    const float4* xs  = (const float4*)(smem + SM_XS);
    #pragma unroll
    for (int it = 0; it < 16; it++) {
      int idx = tid + it * 512;
      int m = idx >> 6, kq = idx & 63;
      int k = kq * 4;
      float4 x = xs[m];
      uint32_t hw[2];
      #pragma unroll
      for (int u = 0; u < 2; u++) {
        float h[2];
        #pragma unroll
        for (int v = 0; v < 2; v++) {
          float4 w = w1t[k + u * 2 + v];
          float hh = fmaf(x.x, w.x, fmaf(x.y, w.y, fmaf(x.z, w.z, fmaf(x.w, w.w, sb1[k + u * 2 + v]))));
          h[v] = fmaxf(hh, 0.f);
        }
        asm("cvt.rn.f16x2.f32 %0, %1, %2;" : "=r"(hw[u]) : "f"(h[1]), "f"(h[0]));
      }
      *(uint2*)(smem + SM_A + (uint32_t)m * LDAB + (uint32_t)k * 2) = make_uint2(hw[0], hw[1]);
    }
  }
  __syncthreads();

  // ---- main loop: 16 k-iters, hi+lo per iter, 2-stage cp.async ----
  int w = tid >> 5, lane = tid & 31;
  int wm = w >> 2, wn = w & 3;
  float acc[2][8][4];
  #pragma unroll
  for (int i = 0; i < 2; i++)
    #pragma unroll
    for (int j = 0; j < 8; j++)
      #pragma unroll
      for (int q = 0; q < 4; q++) acc[i][j][q] = 0.f;

  uint32_t a_lrow = (uint32_t)(lane & 15);
  uint32_t a_koff = (lane & 16) ? 16u : 0u;
  uint32_t b_noff = (uint32_t)(wn * 64 + ((lane & 16) ? 8 : 0)) * 2;

  for (int s = 0; s < 16; s++) {
    int buf = s & 1;
    asm volatile("cp.async.wait_group 0;" ::: "memory");
    __syncthreads();
    if (s + 1 < 16) {
      int k1 = (s + 1) * 16;
      const __half* src = (cp_row < 16) ? &g_B[t][0][k1 + cp_row][cp_c]
                                        : &g_B[t][1][k1 + cp_row - 16][cp_c];
      uint32_t dst = sb + SM_SB + (uint32_t)(1 - buf) * STAGE +
                     (uint32_t)cp_row * LDAB + (uint32_t)cp_c * 2;
      cp16(dst, src);
      cp16(dst + 16, src + 8);
    }
    asm volatile("cp.async.commit_group;" ::: "memory");

    // A fragments (shared across hi and lo passes)
    uint32_t abase = sb + SM_A + (uint32_t)s * 32 + a_koff;
    uint32_t ar[2][4];
    #pragma unroll
    for (int i = 0; i < 2; i++)
      ldm_x4(ar[i], abase + (uint32_t)(wm * 32 + i * 16 + a_lrow) * LDAB);

    uint32_t bst = sb + SM_SB + (uint32_t)buf * STAGE + (uint32_t)(lane & 15) * LDAB + b_noff;
    #pragma unroll
    for (int half = 0; half < 2; half++) {
      uint32_t bbase = bst + (uint32_t)half * (16 * LDAB);
      uint32_t br[4][4];
      #pragma unroll
      for (int j = 0; j < 4; j++) ldm_x4t(br[j], bbase + (uint32_t)j * 32);
      #pragma unroll
      for (int i = 0; i < 2; i++)
        #pragma unroll
        for (int j = 0; j < 4; j++) {
          mma16816(acc[i][2 * j + 0], ar[i], br[j][0], br[j][1]);
          mma16816(acc[i][2 * j + 1], ar[i], br[j][2], br[j][3]);
        }
    }
  }

  // ---- epilogue: tables + relu + scatter ----
  const float* sB2F = (const float*)(smem + SM_B2F);
  const int* sE  = (const int*)(smem + SM_E);
  const int* sTE = (const int*)(smem + SM_TE);
  const int* sSE = (const int*)(smem + SM_SE);
  #pragma unroll
  for (int i = 0; i < 2; i++) {
    #pragma unroll
    for (int rr = 0; rr < 2; rr++) {
      int ml = wm * 32 + i * 16 + (lane >> 2) + rr * 8;
      int e = sE[ml];
      if (e < 0) continue;
      const float* tcp = &g_tc[sTE[ml]][0];
      const float* scp = &g_sc[sSE[ml]][0];
      float* op = out + (size_t)e * D;
      #pragma unroll
      for (int jn = 0; jn < 8; jn++) {
        int col = wn * 64 + jn * 8 + (lane & 3) * 2;
        float2 tv = *(const float2*)&tcp[col];
        float2 sv = *(const float2*)&scp[col];
        float2 o;
        o.x = fmaxf(acc[i][jn][rr * 2 + 0] + tv.x + sv.x + sB2F[col], 0.f);
        o.y = fmaxf(acc[i][jn][rr * 2 + 1] + tv.y + sv.y + sB2F[col + 1], 0.f);
        *(float2*)&op[col] = o;
      }
    }
  }
}

// ================= launch =================
extern "C" void kernel_launch(void* const* d_in, const int* in_sizes, int n_in,
                              void* d_out, int out_size) {
  const int*   type_ids     = (const int*)d_in[0];
  const int*   source_ids   = (const int*)d_in[1];
  const float* params       = (const float*)d_in[2];
  const float* type_embed   = (const float*)d_in[3];
  const float* source_embed = (const float*)d_in[4];
  const float* W1           = (const float*)d_in[5];
  const float* b1           = (const float*)d_in[6];
  const float* W2           = (const float*)d_in[7];
  const float* b2           = (const float*)d_in[8];
  const float* Wf           = (const float*)d_in[9];
  const float* bf           = (const float*)d_in[10];
  float* out = (float*)d_out;
  int E = in_sizes[0];
  if (E > E_MAX) E = E_MAX;

  cudaFuncSetAttribute(k_main, cudaFuncAttributeMaxDynamicSharedMemorySize, SM_TOTAL);

  int nb = (E + 255) / 256;
  k_hist<<<nb, 256>>>(type_ids, E);
  k_fused<<<173, 256>>>(type_embed, source_embed, b2, Wf, bf, W2, nb);
  k_scatter<<<nb, 256>>>(type_ids, E);

  int tiles = (E + BM - 1) / BM + TT;
  k_main<<<tiles, 512, SM_TOTAL>>>(type_ids, source_ids, params, W1, b1, out);
}

// round 5
// speedup vs baseline: 2.0555x; 1.1570x over previous
#include <cuda_runtime.h>
#include <cuda_fp16.h>
#include <cstdint>

#define D      256
#define TT     9
#define NTYPES 14
#define NSRC   5
#define PMAX   4
#define BM     64
#define E_MAX  131072
#define NBMAX  512

// ---- dynamic SMEM layout (bytes) ----
#define SM_XS   0                    // 64 x float4         1024
#define SM_E    1024
#define SM_TE   1280
#define SM_SE   1536
#define SM_B2F  1792                 // 256 x float         1024
#define SM_W1T  2816                 // 256 x float4        4096
#define SM_B1   6912                 // 256 x float         1024
#define SM_A    7936                 // 64 x 528B          33792
#define SM_SB   41728                // 2 stages x 32 x 528B = 33792
#define SM_TOTAL 75520
#define LDAB    528                  // row pitch bytes
#define STAGE   16896                // 32 rows x 528

__constant__ int   c_base_map[NTYPES] = {0,0,0,1,1,1,2,2,3,4,5,6,7,8};
__constant__ int   c_pcount[TT]       = {2,2,1,1,1,1,3,2,4};
__constant__ float c_scales[TT][PMAX] = {
  {1.f,1e-6f,1.f,1.f},{1.f,1e-6f,1.f,1.f},{1.f,1.f,1.f,1.f},
  {1000.f,1.f,1.f,1.f},{1e-12f,1.f,1.f,1.f},{1e-9f,1.f,1.f,1.f},
  {1.f,1.f,1.f,1.f},{1e-3f,1e-3f,1.f,1.f},{1.f,1.f,1e9f,1.f}
};

// ---- device scratch ----
__device__ int   g_part[NBMAX][TT];
__device__ int   g_bbase[NBMAX][TT];
__device__ int   g_counts[TT];
__device__ int   g_offsets[TT+1];
__device__ int   g_tile_off[TT+1];
__device__ int   g_perm[E_MAX];
__device__ __align__(16) __half g_B[TT][2][256][256];  // [t][hi/lo][k][n]
__device__ float g_b2f[TT][D];
__device__ float g_tc[NTYPES][D];
__device__ float g_sc[NSRC][D];

// ================= PTX helpers =================
__device__ __forceinline__ uint32_t smem_u32(const void* p) {
  uint32_t a;
  asm("{ .reg .u64 t; cvta.to.shared.u64 t, %1; cvt.u32.u64 %0, t; }" : "=r"(a) : "l"(p));
  return a;
}
__device__ __forceinline__ void cp16(uint32_t dst, const void* src) {
  asm volatile("cp.async.cg.shared.global [%0], [%1], 16;" :: "r"(dst), "l"(src) : "memory");
}
__device__ __forceinline__ void ldm_x4(uint32_t* r, uint32_t a) {
  asm volatile("ldmatrix.sync.aligned.m8n8.x4.shared.b16 {%0,%1,%2,%3}, [%4];"
    : "=r"(r[0]),"=r"(r[1]),"=r"(r[2]),"=r"(r[3]) : "r"(a));
}
__device__ __forceinline__ void ldm_x4t(uint32_t* r, uint32_t a) {
  asm volatile("ldmatrix.sync.aligned.m8n8.x4.trans.shared.b16 {%0,%1,%2,%3}, [%4];"
    : "=r"(r[0]),"=r"(r[1]),"=r"(r[2]),"=r"(r[3]) : "r"(a));
}
__device__ __forceinline__ void mma16816(float* c, const uint32_t* a, uint32_t b0, uint32_t b1) {
  asm("mma.sync.aligned.m16n8k16.row.col.f32.f16.f16.f32 "
      "{%0,%1,%2,%3}, {%4,%5,%6,%7}, {%8,%9}, {%0,%1,%2,%3};"
      : "+f"(c[0]),"+f"(c[1]),"+f"(c[2]),"+f"(c[3])
      : "r"(a[0]),"r"(a[1]),"r"(a[2]),"r"(a[3]), "r"(b0),"r"(b1));
}

// ================= launch 0: per-block histogram =================
__global__ void k_hist(const int* __restrict__ type_ids, int E) {
  __shared__ int lh[TT];
  int tid = threadIdx.x, b = blockIdx.x;
  if (tid < TT) lh[tid] = 0;
  __syncthreads();
  int e = b * blockDim.x + tid;
  if (e < E) atomicAdd(&lh[c_base_map[type_ids[e]]], 1);
  __syncthreads();
  if (tid < TT) g_part[b][tid] = lh[tid];
}

// ================= launch 1: fused w2f + tables + parallel scan =================
__global__ void k_fused(const float* __restrict__ te, const float* __restrict__ se,
                        const float* __restrict__ b2, const float* __restrict__ Wf,
                        const float* __restrict__ bf, const float* __restrict__ W2,
                        int nb) {
  int bx = blockIdx.x, d = threadIdx.x;
  if (bx < 144) {
    // ---- W2f = W2[t] @ Wf[512:768], fp16 hi + fp16 lo ----
    __shared__ float sW2[16][D];
    int t = bx >> 4, kg = bx & 15;
    for (int kk = 0; kk < 16; kk++)
      sW2[kk][d] = W2[(t * D + kg * 16 + kk) * D + d];
    __syncthreads();
    float acc[16];
    #pragma unroll
    for (int kk = 0; kk < 16; kk++) acc[kk] = 0.f;
    const float* wb = Wf + 512 * D + d;
    for (int dp = 0; dp < D; dp++) {
      float wf = wb[dp * D];
      #pragma unroll
      for (int kk = 0; kk < 16; kk++) acc[kk] = fmaf(sW2[kk][dp], wf, acc[kk]);
    }
    #pragma unroll
    for (int kk = 0; kk < 16; kk++) {
      int k = kg * 16 + kk;
      float v = acc[kk];
      __half hi = __float2half(v);
      __half lo = __float2half(v - __half2float(hi));
      g_B[t][0][k][d] = hi;
      g_B[t][1][k][d] = lo;
    }
  } else if (bx < 172) {
    // ---- embedding / bias tables ----
    __shared__ float row[D];
    int r = bx - 144;
    const float* src; const float* wbase; float* dst; float acc;
    if (r < NTYPES)             { src = te + r * D;            wbase = Wf;           dst = &g_tc[r][0]; acc = 0.f; }
    else if (r < NTYPES + NSRC) { int s = r - NTYPES; src = se + s * D; wbase = Wf + 256 * D; dst = &g_sc[s][0]; acc = 0.f; }
    else                        { int t = r - NTYPES - NSRC; src = b2 + t * D; wbase = Wf + 512 * D; dst = &g_b2f[t][0]; acc = bf[d]; }
    row[d] = src[d];
    __syncthreads();
    #pragma unroll 8
    for (int k = 0; k < D; k++) acc = fmaf(row[k], wbase[k * D + d], acc);
    dst[d] = acc;
  } else {
    // ---- parallel scan: warp w handles types w, w+8 ----
    int lane = d & 31, w = d >> 5;
    for (int t = w; t < TT; t += 8) {
      int carry = 0;
      for (int c = 0; c < nb; c += 32) {
        int idx = c + lane;
        int orig = (idx < nb) ? g_part[idx][t] : 0;
        int v = orig;
        #pragma unroll
        for (int sft = 1; sft < 32; sft <<= 1) {
          int u = __shfl_up_sync(0xffffffffu, v, sft);
          if (lane >= sft) v += u;
        }
        if (idx < nb) g_bbase[idx][t] = carry + v - orig;
        carry += __shfl_sync(0xffffffffu, v, 31);
      }
      if (lane == 0) g_counts[t] = carry;
    }
    __syncthreads();
    if (d == 0) {
      int off = 0, toff = 0;
      for (int t = 0; t < TT; t++) {
        g_offsets[t] = off; g_tile_off[t] = toff;
        off += g_counts[t];
        toff += (g_counts[t] + BM - 1) / BM;
      }
      g_offsets[TT] = off; g_tile_off[TT] = toff;
    }
  }
}

// ================= launch 2: scatter =================
__global__ void k_scatter(const int* __restrict__ type_ids, int E) {
  __shared__ int lh[TT];
  int tid = threadIdx.x, b = blockIdx.x;
  if (tid < TT) lh[tid] = 0;
  __syncthreads();
  int e = b * blockDim.x + tid;
  if (e < E) {
    int t = c_base_map[type_ids[e]];
    int lpos = atomicAdd(&lh[t], 1);
    g_perm[g_offsets[t] + g_bbase[b][t] + lpos] = e;
  }
}

// ================= launch 3: main HMMA kernel =================
// 256 threads = 8 warps, warp grid 2(M) x 4(N); warp tile 32x64; CTA tile 64x256.
// 2 CTAs/SM (regs capped at 128 via launch bounds).
__global__ __launch_bounds__(256, 2) void k_main(
    const int* __restrict__ type_ids, const int* __restrict__ source_ids,
    const float* __restrict__ params, const float* __restrict__ W1,
    const float* __restrict__ b1, float* __restrict__ out) {
  extern __shared__ char smem[];
  int bx = blockIdx.x;
  if (bx >= g_tile_off[TT]) return;
  int t = 0;
  while (bx >= g_tile_off[t + 1]) t++;
  int lt = bx - g_tile_off[t], m0 = lt * BM, cnt = g_counts[t], base = g_offsets[t];
  int tid = threadIdx.x;
  uint32_t sb = smem_u32(smem);

  // prefetch k-iter 0 (B hi rows 0-15, lo rows 16-31) into stage 0
  int cp_row = tid >> 3, cp_c = (tid & 7) * 32;   // 32 halves = 64B per thread
  {
    const __half* src = (cp_row < 16) ? &g_B[t][0][cp_row][cp_c]
                                      : &g_B[t][1][cp_row - 16][cp_c];
    uint32_t dst = sb + SM_SB + (uint32_t)cp_row * LDAB + (uint32_t)cp_c * 2;
    cp16(dst, src);       cp16(dst + 16, src + 8);
    cp16(dst + 32, src + 16); cp16(dst + 48, src + 24);
    asm volatile("cp.async.commit_group;" ::: "memory");
  }

  // metadata + weights
  if (tid < 64) {
    int gm = m0 + tid; int e = -1, tev = 0, sev = 0;
    float4 xv = {0.f, 0.f, 0.f, 0.f};
    if (gm < cnt) {
      e = g_perm[base + gm]; tev = type_ids[e]; sev = source_ids[e];
      int pc = c_pcount[t];
      float4 p4 = *(const float4*)&params[e * PMAX];
      xv.x = p4.x / c_scales[t][0];
      xv.y = pc > 1 ? p4.y / c_scales[t][1] : 0.f;
      xv.z = pc > 2 ? p4.z / c_scales[t][2] : 0.f;
      xv.w = pc > 3 ? p4.w / c_scales[t][3] : 0.f;
    }
    ((float4*)(smem + SM_XS))[tid] = xv;
    ((int*)(smem + SM_E))[tid]  = e;
    ((int*)(smem + SM_TE))[tid] = tev;
    ((int*)(smem + SM_SE))[tid] = sev;
  }
  {
    int k = tid;
    float4 w;
    w.x = W1[(t * PMAX + 0) * D + k];
    w.y = W1[(t * PMAX + 1) * D + k];
    w.z = W1[(t * PMAX + 2) * D + k];
    w.w = W1[(t * PMAX + 3) * D + k];
    ((float4*)(smem + SM_W1T))[k] = w;
    ((float*)(smem + SM_B1))[k]  = b1[t * D + k];
    ((float*)(smem + SM_B2F))[k] = g_b2f[t][k];
  }
  __syncthreads();

  // ---- A-phase: h = relu(x@W1+b1) -> fp16 in SMEM (64 rows x 256 cols) ----
  {
    const float4* w1t = (const float4*)(smem + SM_W1T);
    const float*  sb1 = (const float*)(smem + SM_B1);
    const float4* xs  = (const float4*)(smem + SM_XS);
    #pragma unroll
    for (int it = 0; it < 16; it++) {
      int idx = tid + it * 256;
      int m = idx >> 6, kq = idx & 63;
      int k = kq * 4;
      float4 x = xs[m];
      uint32_t hw[2];
      #pragma unroll
      for (int u = 0; u < 2; u++) {
        float h[2];
        #pragma unroll
        for (int v = 0; v < 2; v++) {
          float4 w = w1t[k + u * 2 + v];
          float hh = fmaf(x.x, w.x, fmaf(x.y, w.y, fmaf(x.z, w.z, fmaf(x.w, w.w, sb1[k + u * 2 + v]))));
          h[v] = fmaxf(hh, 0.f);
        }
        asm("cvt.rn.f16x2.f32 %0, %1, %2;" : "=r"(hw[u]) : "f"(h[1]), "f"(h[0]));
      }
      *(uint2*)(smem + SM_A + (uint32_t)m * LDAB + (uint32_t)k * 2) = make_uint2(hw[0], hw[1]);
    }
  }
  __syncthreads();

  // ---- main loop: 16 k-iters, hi+lo per iter, 2-stage cp.async ----
  int w = tid >> 5, lane = tid & 31;
  int wm = w >> 2, wn = w & 3;
  float acc[2][8][4];
  #pragma unroll
  for (int i = 0; i < 2; i++)
    #pragma unroll
    for (int j = 0; j < 8; j++)
      #pragma unroll
      for (int q = 0; q < 4; q++) acc[i][j][q] = 0.f;

  uint32_t a_lrow = (uint32_t)(lane & 15);
  uint32_t a_koff = (lane & 16) ? 16u : 0u;
  uint32_t b_noff = (uint32_t)(wn * 64 + ((lane & 16) ? 8 : 0)) * 2;

  for (int s = 0; s < 16; s++) {
    int buf = s & 1;
    asm volatile("cp.async.wait_group 0;" ::: "memory");
    __syncthreads();
    if (s + 1 < 16) {
      int k1 = (s + 1) * 16;
      const __half* src = (cp_row < 16) ? &g_B[t][0][k1 + cp_row][cp_c]
                                        : &g_B[t][1][k1 + cp_row - 16][cp_c];
      uint32_t dst = sb + SM_SB + (uint32_t)(1 - buf) * STAGE +
                     (uint32_t)cp_row * LDAB + (uint32_t)cp_c * 2;
      cp16(dst, src);       cp16(dst + 16, src + 8);
      cp16(dst + 32, src + 16); cp16(dst + 48, src + 24);
    }
    asm volatile("cp.async.commit_group;" ::: "memory");

    // A fragments (shared across hi and lo passes)
    uint32_t abase = sb + SM_A + (uint32_t)s * 32 + a_koff;
    uint32_t ar[2][4];
    #pragma unroll
    for (int i = 0; i < 2; i++)
      ldm_x4(ar[i], abase + (uint32_t)(wm * 32 + i * 16 + a_lrow) * LDAB);

    uint32_t bst = sb + SM_SB + (uint32_t)buf * STAGE + (uint32_t)(lane & 15) * LDAB + b_noff;
    #pragma unroll
    for (int half = 0; half < 2; half++) {
      uint32_t bbase = bst + (uint32_t)half * (16 * LDAB);
      uint32_t br[4][4];
      #pragma unroll
      for (int j = 0; j < 4; j++) ldm_x4t(br[j], bbase + (uint32_t)j * 32);
      #pragma unroll
      for (int i = 0; i < 2; i++)
        #pragma unroll
        for (int j = 0; j < 4; j++) {
          mma16816(acc[i][2 * j + 0], ar[i], br[j][0], br[j][1]);
          mma16816(acc[i][2 * j + 1], ar[i], br[j][2], br[j][3]);
        }
    }
  }

  // ---- epilogue: tables + relu + scatter ----
  const float* sB2F = (const float*)(smem + SM_B2F);
  const int* sE  = (const int*)(smem + SM_E);
  const int* sTE = (const int*)(smem + SM_TE);
  const int* sSE = (const int*)(smem + SM_SE);
  #pragma unroll
  for (int i = 0; i < 2; i++) {
    #pragma unroll
    for (int rr = 0; rr < 2; rr++) {
      int ml = wm * 32 + i * 16 + (lane >> 2) + rr * 8;
      int e = sE[ml];
      if (e < 0) continue;
      const float* tcp = &g_tc[sTE[ml]][0];
      const float* scp = &g_sc[sSE[ml]][0];
      float* op = out + (size_t)e * D;
      #pragma unroll
      for (int jn = 0; jn < 8; jn++) {
        int col = wn * 64 + jn * 8 + (lane & 3) * 2;
        float2 tv = *(const float2*)&tcp[col];
        float2 sv = *(const float2*)&scp[col];
        float2 o;
        o.x = fmaxf(acc[i][jn][rr * 2 + 0] + tv.x + sv.x + sB2F[col], 0.f);
        o.y = fmaxf(acc[i][jn][rr * 2 + 1] + tv.y + sv.y + sB2F[col + 1], 0.f);
        *(float2*)&op[col] = o;
      }
    }
  }
}

// ================= launch =================
extern "C" void kernel_launch(void* const* d_in, const int* in_sizes, int n_in,
                              void* d_out, int out_size) {
  const int*   type_ids     = (const int*)d_in[0];
  const int*   source_ids   = (const int*)d_in[1];
  const float* params       = (const float*)d_in[2];
  const float* type_embed   = (const float*)d_in[3];
  const float* source_embed = (const float*)d_in[4];
  const float* W1           = (const float*)d_in[5];
  const float* b1           = (const float*)d_in[6];
  const float* W2           = (const float*)d_in[7];
  const float* b2           = (const float*)d_in[8];
  const float* Wf           = (const float*)d_in[9];
  const float* bf           = (const float*)d_in[10];
  float* out = (float*)d_out;
  int E = in_sizes[0];
  if (E > E_MAX) E = E_MAX;

  cudaFuncSetAttribute(k_main, cudaFuncAttributeMaxDynamicSharedMemorySize, SM_TOTAL);

  int nb = (E + 255) / 256;
  k_hist<<<nb, 256>>>(type_ids, E);
  k_fused<<<173, 256>>>(type_embed, source_embed, b2, Wf, bf, W2, nb);
  k_scatter<<<nb, 256>>>(type_ids, E);

  int tiles = (E + BM - 1) / BM + TT;
  k_main<<<tiles, 256, SM_TOTAL>>>(type_ids, source_ids, params, W1, b1, out);
}

// round 6
// speedup vs baseline: 2.3474x; 1.1420x over previous
#include <cuda_runtime.h>
#include <cuda_fp16.h>
#include <cstdint>

#define D      256
#define TT     9
#define NTYPES 14
#define NSRC   5
#define PMAX   4
#define BM     128
#define E_MAX  131072
#define NBMAX  512
#define NCTA   148

// ---- dynamic SMEM layout (bytes) ----
#define SM_XS   0                    // 128 x float4        2048
#define SM_E    2048
#define SM_TE   2560
#define SM_SE   3072
#define SM_B2F  3584                 // 256 x float         1024
#define SM_W1T  4608                 // 256 x float4        4096
#define SM_B1   8704                 // 256 x float         1024
#define SM_A    9728                 // 128 x 528B         67584
#define SM_SB   77312                // 2(hi/lo) x 256k x 272B = 139264
#define SM_TOTAL 216576
#define LDAB    528                  // A row pitch
#define LDB     272                  // B row pitch (128 halves + pad)
#define BHALF   69632                // 256*LDB

__constant__ int   c_base_map[NTYPES] = {0,0,0,1,1,1,2,2,3,4,5,6,7,8};
__constant__ int   c_pcount[TT]       = {2,2,1,1,1,1,3,2,4};
__constant__ float c_scales[TT][PMAX] = {
  {1.f,1e-6f,1.f,1.f},{1.f,1e-6f,1.f,1.f},{1.f,1.f,1.f,1.f},
  {1000.f,1.f,1.f,1.f},{1e-12f,1.f,1.f,1.f},{1e-9f,1.f,1.f,1.f},
  {1.f,1.f,1.f,1.f},{1e-3f,1e-3f,1.f,1.f},{1.f,1.f,1e9f,1.f}
};

// ---- device scratch ----
__device__ int   g_part[NBMAX][TT];
__device__ int   g_bbase[NBMAX][TT];
__device__ int   g_counts[TT];
__device__ int   g_offsets[TT+1];
__device__ int   g_tile_off[TT+1];
__device__ int   g_perm[E_MAX];
__device__ __align__(16) __half g_B[TT][2][256][256];  // [t][hi/lo][k][n]
__device__ float g_b2f[TT][D];
__device__ float g_tc[NTYPES][D];
__device__ float g_sc[NSRC][D];

// ================= PTX helpers =================
__device__ __forceinline__ uint32_t smem_u32(const void* p) {
  uint32_t a;
  asm("{ .reg .u64 t; cvta.to.shared.u64 t, %1; cvt.u32.u64 %0, t; }" : "=r"(a) : "l"(p));
  return a;
}
__device__ __forceinline__ void cp16(uint32_t dst, const void* src) {
  asm volatile("cp.async.cg.shared.global [%0], [%1], 16;" :: "r"(dst), "l"(src) : "memory");
}
__device__ __forceinline__ void ldm_x4(uint32_t* r, uint32_t a) {
  asm volatile("ldmatrix.sync.aligned.m8n8.x4.shared.b16 {%0,%1,%2,%3}, [%4];"
    : "=r"(r[0]),"=r"(r[1]),"=r"(r[2]),"=r"(r[3]) : "r"(a));
}
__device__ __forceinline__ void ldm_x4t(uint32_t* r, uint32_t a) {
  asm volatile("ldmatrix.sync.aligned.m8n8.x4.trans.shared.b16 {%0,%1,%2,%3}, [%4];"
    : "=r"(r[0]),"=r"(r[1]),"=r"(r[2]),"=r"(r[3]) : "r"(a));
}
__device__ __forceinline__ void mma16816(float* c, const uint32_t* a, uint32_t b0, uint32_t b1) {
  asm("mma.sync.aligned.m16n8k16.row.col.f32.f16.f16.f32 "
      "{%0,%1,%2,%3}, {%4,%5,%6,%7}, {%8,%9}, {%0,%1,%2,%3};"
      : "+f"(c[0]),"+f"(c[1]),"+f"(c[2]),"+f"(c[3])
      : "r"(a[0]),"r"(a[1]),"r"(a[2]),"r"(a[3]), "r"(b0),"r"(b1));
}

// ================= launch 0: per-block histogram =================
__global__ void k_hist(const int* __restrict__ type_ids, int E) {
  __shared__ int lh[TT];
  int tid = threadIdx.x, b = blockIdx.x;
  if (tid < TT) lh[tid] = 0;
  __syncthreads();
  int e = b * blockDim.x + tid;
  if (e < E) atomicAdd(&lh[c_base_map[type_ids[e]]], 1);
  __syncthreads();
  if (tid < TT) g_part[b][tid] = lh[tid];
}

// ================= launch 1: fused w2f + tables + parallel scan =================
__global__ void k_fused(const float* __restrict__ te, const float* __restrict__ se,
                        const float* __restrict__ b2, const float* __restrict__ Wf,
                        const float* __restrict__ bf, const float* __restrict__ W2,
                        int nb) {
  int bx = blockIdx.x, d = threadIdx.x;
  if (bx < 144) {
    __shared__ float sW2[16][D];
    int t = bx >> 4, kg = bx & 15;
    for (int kk = 0; kk < 16; kk++)
      sW2[kk][d] = W2[(t * D + kg * 16 + kk) * D + d];
    __syncthreads();
    float acc[16];
    #pragma unroll
    for (int kk = 0; kk < 16; kk++) acc[kk] = 0.f;
    const float* wb = Wf + 512 * D + d;
    for (int dp = 0; dp < D; dp++) {
      float wf = wb[dp * D];
      #pragma unroll
      for (int kk = 0; kk < 16; kk++) acc[kk] = fmaf(sW2[kk][dp], wf, acc[kk]);
    }
    #pragma unroll
    for (int kk = 0; kk < 16; kk++) {
      int k = kg * 16 + kk;
      float v = acc[kk];
      __half hi = __float2half(v);
      __half lo = __float2half(v - __half2float(hi));
      g_B[t][0][k][d] = hi;
      g_B[t][1][k][d] = lo;
    }
  } else if (bx < 172) {
    __shared__ float row[D];
    int r = bx - 144;
    const float* src; const float* wbase; float* dst; float acc;
    if (r < NTYPES)             { src = te + r * D;            wbase = Wf;           dst = &g_tc[r][0]; acc = 0.f; }
    else if (r < NTYPES + NSRC) { int s = r - NTYPES; src = se + s * D; wbase = Wf + 256 * D; dst = &g_sc[s][0]; acc = 0.f; }
    else                        { int t = r - NTYPES - NSRC; src = b2 + t * D; wbase = Wf + 512 * D; dst = &g_b2f[t][0]; acc = bf[d]; }
    row[d] = src[d];
    __syncthreads();
    #pragma unroll 8
    for (int k = 0; k < D; k++) acc = fmaf(row[k], wbase[k * D + d], acc);
    dst[d] = acc;
  } else {
    int lane = d & 31, w = d >> 5;
    for (int t = w; t < TT; t += 8) {
      int carry = 0;
      for (int c = 0; c < nb; c += 32) {
        int idx = c + lane;
        int orig = (idx < nb) ? g_part[idx][t] : 0;
        int v = orig;
        #pragma unroll
        for (int sft = 1; sft < 32; sft <<= 1) {
          int u = __shfl_up_sync(0xffffffffu, v, sft);
          if (lane >= sft) v += u;
        }
        if (idx < nb) g_bbase[idx][t] = carry + v - orig;
        carry += __shfl_sync(0xffffffffu, v, 31);
      }
      if (lane == 0) g_counts[t] = carry;
    }
    __syncthreads();
    if (d == 0) {
      int off = 0, toff = 0;
      for (int t = 0; t < TT; t++) {
        g_offsets[t] = off; g_tile_off[t] = toff;
        off += g_counts[t];
        toff += (g_counts[t] + BM - 1) / BM;
      }
      g_offsets[TT] = off; g_tile_off[TT] = toff;
    }
  }
}

// ================= launch 2: scatter =================
__global__ void k_scatter(const int* __restrict__ type_ids, int E) {
  __shared__ int lh[TT];
  int tid = threadIdx.x, b = blockIdx.x;
  if (tid < TT) lh[tid] = 0;
  __syncthreads();
  int e = b * blockDim.x + tid;
  if (e < E) {
    int t = c_base_map[type_ids[e]];
    int lpos = atomicAdd(&lh[t], 1);
    g_perm[g_offsets[t] + g_bbase[b][t] + lpos] = e;
  }
}

// ================= launch 3: persistent-B HMMA kernel =================
// 148 worker CTAs x 512 threads. Work item = (nhalf, tile); item order is
// half-major so consecutive items share expert type -> B stays resident.
// CTA tile 128M x 128N, 16 warps, warp tile 32x32, K=256 x {hi,lo}.
__global__ __launch_bounds__(512, 1) void k_main(
    const int* __restrict__ type_ids, const int* __restrict__ source_ids,
    const float* __restrict__ params, const float* __restrict__ W1,
    const float* __restrict__ b1, float* __restrict__ out,
    int ntub, int chunk) {
  extern __shared__ char smem[];
  uint32_t sb = smem_u32(smem);
  int tid = threadIdx.x;
  int w = tid >> 5, lane = tid & 31;
  int wm = w >> 2, wn = w & 3;

  uint32_t a_lrow = (uint32_t)(lane & 15);
  uint32_t a_koff = (lane & 16) ? 16u : 0u;
  uint32_t b_coff = (uint32_t)(wn * 64 + ((lane & 16) ? 16 : 0));

  int w0 = blockIdx.x * chunk;
  int w1 = min(w0 + chunk, 2 * ntub);
  int cur_t = -1, cur_half = -1;
  int ntiles = g_tile_off[TT];

  for (int item = w0; item < w1; item++) {
    int nhalf = (item >= ntub) ? 1 : 0;
    int tile  = item - nhalf * ntub;
    if (tile >= ntiles) continue;
    int t = 0;
    while (tile >= g_tile_off[t + 1]) t++;
    int m0 = (tile - g_tile_off[t]) * BM;
    int cnt = g_counts[t], base = g_offsets[t];
    int n0 = nhalf * 128;

    __syncthreads();   // previous item fully done with smem

    bool newT = (t != cur_t);
    bool newB = newT || (nhalf != cur_half);
    if (newT && tid < 256) {
      int k = tid;
      float4 wv;
      wv.x = W1[(t * PMAX + 0) * D + k];
      wv.y = W1[(t * PMAX + 1) * D + k];
      wv.z = W1[(t * PMAX + 2) * D + k];
      wv.w = W1[(t * PMAX + 3) * D + k];
      ((float4*)(smem + SM_W1T))[k] = wv;
      ((float*)(smem + SM_B1))[k]  = b1[t * D + k];
      ((float*)(smem + SM_B2F))[k] = g_b2f[t][k];
    }
    if (newB) {
      // 512 rows (hi 256 + lo 256) x 256B, one row per thread
      int hl = tid >> 8, k = tid & 255;
      const __half* src = &g_B[t][hl][k][n0];
      uint32_t dst = sb + SM_SB + (uint32_t)tid * LDB;
      #pragma unroll
      for (int j = 0; j < 16; j++) cp16(dst + j * 16, src + j * 8);
      asm volatile("cp.async.commit_group;" ::: "memory");
    }
    cur_t = t; cur_half = nhalf;

    // per-row metadata
    if (tid < 128) {
      int gm = m0 + tid; int e = -1, tev = 0, sev = 0;
      float4 xv = {0.f, 0.f, 0.f, 0.f};
      if (gm < cnt) {
        e = g_perm[base + gm]; tev = type_ids[e]; sev = source_ids[e];
        int pc = c_pcount[t];
        float4 p4 = *(const float4*)&params[e * PMAX];
        xv.x = p4.x / c_scales[t][0];
        xv.y = pc > 1 ? p4.y / c_scales[t][1] : 0.f;
        xv.z = pc > 2 ? p4.z / c_scales[t][2] : 0.f;
        xv.w = pc > 3 ? p4.w / c_scales[t][3] : 0.f;
      }
      ((float4*)(smem + SM_XS))[tid] = xv;
      ((int*)(smem + SM_E))[tid]  = e;
      ((int*)(smem + SM_TE))[tid] = tev;
      ((int*)(smem + SM_SE))[tid] = sev;
    }
    __syncthreads();   // W1/meta visible

    // ---- A-phase: h = relu(x@W1+b1) -> fp16 in SMEM (128 x 256) ----
    {
      const float4* w1t = (const float4*)(smem + SM_W1T);
      const float*  sb1 = (const float*)(smem + SM_B1);
      const float4* xs  = (const float4*)(smem + SM_XS);
      #pragma unroll
      for (int it = 0; it < 16; it++) {
        int idx = tid + it * 512;
        int m = idx >> 6, kq = idx & 63;
        int k = kq * 4;
        float4 x = xs[m];
        uint32_t hw[2];
        #pragma unroll
        for (int u = 0; u < 2; u++) {
          float h[2];
          #pragma unroll
          for (int v = 0; v < 2; v++) {
            float4 wv = w1t[k + u * 2 + v];
            float hh = fmaf(x.x, wv.x, fmaf(x.y, wv.y, fmaf(x.z, wv.z, fmaf(x.w, wv.w, sb1[k + u * 2 + v]))));
            h[v] = fmaxf(hh, 0.f);
          }
          asm("cvt.rn.f16x2.f32 %0, %1, %2;" : "=r"(hw[u]) : "f"(h[1]), "f"(h[0]));
        }
        *(uint2*)(smem + SM_A + (uint32_t)m * LDAB + (uint32_t)k * 2) = make_uint2(hw[0], hw[1]);
      }
    }
    asm volatile("cp.async.wait_group 0;" ::: "memory");
    __syncthreads();   // A + B ready

    // ---- MMA: 16 k-iters, no syncs ----
    float acc[2][4][4];
    #pragma unroll
    for (int i = 0; i < 2; i++)
      #pragma unroll
      for (int j = 0; j < 4; j++)
        #pragma unroll
        for (int q = 0; q < 4; q++) acc[i][j][q] = 0.f;

    #pragma unroll 4
    for (int s = 0; s < 16; s++) {
      uint32_t abase = sb + SM_A + (uint32_t)s * 32 + a_koff;
      uint32_t ar[2][4];
      #pragma unroll
      for (int i = 0; i < 2; i++)
        ldm_x4(ar[i], abase + (uint32_t)(wm * 32 + i * 16 + a_lrow) * LDAB);
      #pragma unroll
      for (int half = 0; half < 2; half++) {
        uint32_t bbase = sb + SM_SB + (uint32_t)half * BHALF +
                         (uint32_t)(s * 16 + (lane & 15)) * LDB + b_coff;
        uint32_t br0[4], br1[4];
        ldm_x4t(br0, bbase);
        ldm_x4t(br1, bbase + 32);
        #pragma unroll
        for (int i = 0; i < 2; i++) {
          mma16816(acc[i][0], ar[i], br0[0], br0[1]);
          mma16816(acc[i][1], ar[i], br0[2], br0[3]);
          mma16816(acc[i][2], ar[i], br1[0], br1[1]);
          mma16816(acc[i][3], ar[i], br1[2], br1[3]);
        }
      }
    }

    // ---- epilogue ----
    const float* sB2F = (const float*)(smem + SM_B2F);
    const int* sE  = (const int*)(smem + SM_E);
    const int* sTE = (const int*)(smem + SM_TE);
    const int* sSE = (const int*)(smem + SM_SE);
    #pragma unroll
    for (int i = 0; i < 2; i++) {
      #pragma unroll
      for (int rr = 0; rr < 2; rr++) {
        int ml = wm * 32 + i * 16 + rr * 8 + (lane >> 2);
        int e = sE[ml];
        if (e < 0) continue;
        const float* tcp = &g_tc[sTE[ml]][0];
        const float* scp = &g_sc[sSE[ml]][0];
        float* op = out + (size_t)e * D;
        #pragma unroll
        for (int j = 0; j < 4; j++) {
          int col = n0 + wn * 32 + j * 8 + (lane & 3) * 2;
          float2 tv = *(const float2*)&tcp[col];
          float2 sv = *(const float2*)&scp[col];
          float2 o;
          o.x = fmaxf(acc[i][j][rr * 2 + 0] + tv.x + sv.x + sB2F[col], 0.f);
          o.y = fmaxf(acc[i][j][rr * 2 + 1] + tv.y + sv.y + sB2F[col + 1], 0.f);
          *(float2*)&op[col] = o;
        }
      }
    }
  }
}

// ================= launch =================
extern "C" void kernel_launch(void* const* d_in, const int* in_sizes, int n_in,
                              void* d_out, int out_size) {
  const int*   type_ids     = (const int*)d_in[0];
  const int*   source_ids   = (const int*)d_in[1];
  const float* params       = (const float*)d_in[2];
  const float* type_embed   = (const float*)d_in[3];
  const float* source_embed = (const float*)d_in[4];
  const float* W1           = (const float*)d_in[5];
  const float* b1           = (const float*)d_in[6];
  const float* W2           = (const float*)d_in[7];
  const float* b2           = (const float*)d_in[8];
  const float* Wf           = (const float*)d_in[9];
  const float* bf           = (const float*)d_in[10];
  float* out = (float*)d_out;
  int E = in_sizes[0];
  if (E > E_MAX) E = E_MAX;

  cudaFuncSetAttribute(k_main, cudaFuncAttributeMaxDynamicSharedMemorySize, SM_TOTAL);

  int nb = (E + 255) / 256;
  k_hist<<<nb, 256>>>(type_ids, E);
  k_fused<<<173, 256>>>(type_embed, source_embed, b2, Wf, bf, W2, nb);
  k_scatter<<<nb, 256>>>(type_ids, E);

  int ntub = (E + BM - 1) / BM + TT;            // upper bound on total tiles
  int chunk = (2 * ntub + NCTA - 1) / NCTA;
  k_main<<<NCTA, 512, SM_TOTAL>>>(type_ids, source_ids, params, W1, b1, out,
                                  ntub, chunk);
}